// round 13
// baseline (speedup 1.0000x reference)
#include <cuda_runtime.h>
#include <cuda_bf16.h>
#include <cstdint>

// PairwiseMax: B=4096, D1=256, D2=256, F=128
// out[b, 0:256]   = x0[b,i] >= 0 ? x0[b,i]*max(x1[b,:]) : x0[b,i]*min(x1[b,:])
// out[b, 256:384] = x2[b,:]
//
// R13 == R12 resubmit (container infra failure, kernel never ran):
// 256-bit global accesses (Blackwell v8.b32) + L2 eviction steering
// (ptxas only allows evict hints on 256-bit ops — discovered R11).
// Geometry = champion R9: 1024 blocks x 128 thr, warp-per-row,
// queue-ordered consumption, REDUX reduction, branchless select.
//  x1/x0 row = 1024B = 32 lanes x 32B -> one v8 load each.
//  x2  row =  512B -> lanes 0-15 predicated v8 load/store.

#define B_ROWS 4096
#define WARPS_PER_BLOCK 4
#define THREADS (WARPS_PER_BLOCK * 32)           // 128
#define BLOCKS (B_ROWS / WARPS_PER_BLOCK)        // 1024

// Monotone map: float total order -> unsigned total order.
__device__ __forceinline__ unsigned enc_ord(float f) {
    unsigned u = __float_as_uint(f);
    return u ^ ((unsigned)((int)u >> 31) | 0x80000000u);
}
__device__ __forceinline__ float dec_ord(unsigned k) {
    return __uint_as_float(k ^ ((unsigned)(((int)~k) >> 31) | 0x80000000u));
}

// 256-bit load, L2 evict-last (pin inputs in L2 across graph replays).
__device__ __forceinline__ void ldg256_el(const float* p, uint32_t* v) {
    asm volatile(
        "ld.global.nc.L2::evict_last.v8.b32 {%0,%1,%2,%3,%4,%5,%6,%7}, [%8];"
        : "=r"(v[0]), "=r"(v[1]), "=r"(v[2]), "=r"(v[3]),
          "=r"(v[4]), "=r"(v[5]), "=r"(v[6]), "=r"(v[7])
        : "l"(p));
}
// 256-bit store, L2 evict-first (write-only output, don't pollute L2).
__device__ __forceinline__ void stg256_ef(float* p, const uint32_t* v) {
    asm volatile(
        "st.global.L2::evict_first.v8.b32 [%0], {%1,%2,%3,%4,%5,%6,%7,%8};"
        :: "l"(p),
           "r"(v[0]), "r"(v[1]), "r"(v[2]), "r"(v[3]),
           "r"(v[4]), "r"(v[5]), "r"(v[6]), "r"(v[7])
        : "memory");
}

__global__ __launch_bounds__(THREADS) void pairwise_max_kernel(
    const float* __restrict__ x0,   // [B, 256]
    const float* __restrict__ x1,   // [B, 256]
    const float* __restrict__ x2,   // [B, 128]
    float* __restrict__ out)        // [B, 384]
{
    const int warp_id = threadIdx.x >> 5;
    const int lane    = threadIdx.x & 31;
    const int row     = blockIdx.x * WARPS_PER_BLOCK + warp_id;  // exact 4096

    const float* x1row  = x1 + (size_t)row * 256;
    const float* x0row  = x0 + (size_t)row * 256;
    const float* x2row  = x2 + (size_t)row * 128;
    float*       outrow = out + (size_t)row * 384;

    // ---- Front-batched 256-bit loads, queue-ordered by consumer ----
    uint32_t a[8], c[8], e[8];
    ldg256_el(x1row + lane * 8, a);          // consumer #1 (reduction)
    ldg256_el(x0row + lane * 8, c);          // consumer #2 (scale)
    const bool has_e = (lane < 16);
    if (has_e) ldg256_el(x2row + lane * 8, e);   // consumer #3 (passthrough)

    // ---- Local reduce over 8 values ----
    float lmx, lmn;
    {
        float f0 = __uint_as_float(a[0]), f1 = __uint_as_float(a[1]);
        float f2 = __uint_as_float(a[2]), f3 = __uint_as_float(a[3]);
        float f4 = __uint_as_float(a[4]), f5 = __uint_as_float(a[5]);
        float f6 = __uint_as_float(a[6]), f7 = __uint_as_float(a[7]);
        lmx = fmaxf(fmaxf(fmaxf(f0, f1), fmaxf(f2, f3)),
                    fmaxf(fmaxf(f4, f5), fmaxf(f6, f7)));
        lmn = fminf(fminf(fminf(f0, f1), fminf(f2, f3)),
                    fminf(fminf(f4, f5), fminf(f6, f7)));
    }

    // ---- Warp reduction via integer REDUX; c,e land underneath ----
    const float mx = dec_ord(__reduce_max_sync(0xFFFFFFFFu, enc_ord(lmx)));
    const float mn = dec_ord(__reduce_min_sync(0xFFFFFFFFu, enc_ord(lmn)));

    // ---- Branchless scale (mx >= mn), 256-bit store ----
    uint32_t o[8];
    #pragma unroll
    for (int i = 0; i < 8; i++) {
        const float cv = __uint_as_float(c[i]);
        o[i] = __float_as_uint(fmaxf(cv * mx, cv * mn));
    }
    stg256_ef(outrow + lane * 8, o);

    // ---- x2 passthrough (lanes 0-15 cover the 512B tail) ----
    if (has_e) stg256_ef(outrow + 256 + lane * 8, e);
}

extern "C" void kernel_launch(void* const* d_in, const int* in_sizes, int n_in,
                              void* d_out, int out_size)
{
    const float* x0 = (const float*)d_in[0];
    const float* x1 = (const float*)d_in[1];
    const float* x2 = (const float*)d_in[2];
    float* out = (float*)d_out;

    pairwise_max_kernel<<<BLOCKS, THREADS>>>(x0, x1, x2, out);
}

// round 14
// speedup vs baseline: 1.0833x; 1.0833x over previous
#include <cuda_runtime.h>
#include <cuda_bf16.h>

// PairwiseMax: B=4096, D1=256, D2=256, F=128
// out[b, 0:256]   = x0[b,i] >= 0 ? x0[b,i]*max(x1[b,:]) : x0[b,i]*min(x1[b,:])
// out[b, 256:384] = x2[b,:]
//
// R14 (terminal): champion R9 config. 14 rounds established this workload
// is launch/latency-floor bound (~6.1-6.5us across ALL structures: occupancy
// 21-71%, grids 128-1536 blocks, SHFL vs REDUX, float4 vs v8, cache hints);
// every pipe idles at <=21%. Best reproduced harness time: 6.144us.
//  - 1024 blocks x 128 threads, warp-per-row (7-vs-6 blocks/SM, 1.2% skew)
//  - 5 front-batched LDG.128, consumed in L1tex-queue order
//  - REDUX.u32 warp reduction on order-preserving keys
//  - branchless select: mx>=mn => o = fmaxf(c*mx, c*mn)

#define B_ROWS 4096
#define WARPS_PER_BLOCK 4
#define THREADS (WARPS_PER_BLOCK * 32)           // 128
#define BLOCKS (B_ROWS / WARPS_PER_BLOCK)        // 1024

// Monotone map: float total order -> unsigned total order.
__device__ __forceinline__ unsigned enc_ord(float f) {
    unsigned u = __float_as_uint(f);
    return u ^ ((unsigned)((int)u >> 31) | 0x80000000u);
}
__device__ __forceinline__ float dec_ord(unsigned k) {
    return __uint_as_float(k ^ ((unsigned)(((int)~k) >> 31) | 0x80000000u));
}

__global__ __launch_bounds__(THREADS) void pairwise_max_kernel(
    const float4* __restrict__ x0v,   // [B, 64] float4
    const float4* __restrict__ x1v,   // [B, 64] float4
    const float4* __restrict__ x2v,   // [B, 32] float4
    float4* __restrict__ outv)        // [B, 96] float4
{
    const int warp_id = threadIdx.x >> 5;
    const int lane    = threadIdx.x & 31;
    const int row     = blockIdx.x * WARPS_PER_BLOCK + warp_id;  // exact 4096

    const float4* x1row  = x1v + (size_t)row * 64;
    const float4* x0row  = x0v + (size_t)row * 64;
    const float4* x2row  = x2v + (size_t)row * 32;
    float4*       outrow = outv + (size_t)row * 96;

    // Issue x1 loads FIRST (their consumers come first), then x0/x2.
    float4 a = x1row[lane];
    float4 b = x1row[lane + 32];
    float4 c = x0row[lane];
    float4 d = x0row[lane + 32];
    float4 e = x2row[lane];

    // First scoreboard wait: only a,b (front of the L1tex queue).
    float lmx = fmaxf(fmaxf(fmaxf(a.x, a.y), fmaxf(a.z, a.w)),
                      fmaxf(fmaxf(b.x, b.y), fmaxf(b.z, b.w)));
    float lmn = fminf(fminf(fminf(a.x, a.y), fminf(a.z, a.w)),
                      fminf(fminf(b.x, b.y), fminf(b.z, b.w)));

    // c, d, e continue landing while REDUX executes.
    const float mx = dec_ord(__reduce_max_sync(0xFFFFFFFFu, enc_ord(lmx)));
    const float mn = dec_ord(__reduce_min_sync(0xFFFFFFFFu, enc_ord(lmn)));

    // Branchless: mx >= mn, so the selected product is the larger one.
    float4 oc, od;
    oc.x = fmaxf(c.x * mx, c.x * mn);
    oc.y = fmaxf(c.y * mx, c.y * mn);
    oc.z = fmaxf(c.z * mx, c.z * mn);
    oc.w = fmaxf(c.w * mx, c.w * mn);
    od.x = fmaxf(d.x * mx, d.x * mn);
    od.y = fmaxf(d.y * mx, d.y * mn);
    od.z = fmaxf(d.z * mx, d.z * mn);
    od.w = fmaxf(d.w * mx, d.w * mn);

    outrow[lane]      = oc;
    outrow[lane + 32] = od;
    outrow[lane + 64] = e;   // x2 passthrough, deepest-queued load consumed last
}

extern "C" void kernel_launch(void* const* d_in, const int* in_sizes, int n_in,
                              void* d_out, int out_size)
{
    const float4* x0v = (const float4*)d_in[0];
    const float4* x1v = (const float4*)d_in[1];
    const float4* x2v = (const float4*)d_in[2];
    float4* outv = (float4*)d_out;

    pairwise_max_kernel<<<BLOCKS, THREADS>>>(x0v, x1v, x2v, outv);
}